// round 10
// baseline (speedup 1.0000x reference)
#include <cuda_runtime.h>

// Gaussian_Forward_Model: 3x3 conv, padding=1 (zeros), kernel built from
// weight (clamped) * weight_factor (clamped), rounded (RNE), min-clamped.
// input: [B=64, C=1, H=512, W=512] fp32
// output: [N_MULT, B, 1, H, W] fp32
//
// R5: back to R1's scalar-halo loads (no SHFL), but with front-batched
// memory-level parallelism: ROWS=4, 4-row register window, loads issued a
// full row-compute ahead of use. regs capped via launch_bounds(128,12).
// Streaming stores; interior strips fully unpredicated.

#define B 64
#define H 512
#define W 512
#define ROWS 4              // output rows per thread
#define TPB 128             // 128 threads * 4 floats = 512 = W

__device__ __forceinline__ float clampf(float v, float lo, float hi) {
    return fminf(fmaxf(v, lo), hi);
}

struct Row {
    float l;    // x-1
    float4 c;   // x..x+3
    float r;    // x+4
};

// Load a full row (center float4 + 2 halo scalars). GUARD covers the y range.
template <bool GUARD>
__device__ __forceinline__ Row load_row(const float* __restrict__ img, int y, int x) {
    Row row;
    if (GUARD) {
        if (y < 0 || y >= H) {
            row.l = 0.f; row.r = 0.f;
            row.c = make_float4(0.f, 0.f, 0.f, 0.f);
            return row;
        }
    }
    const float* p = img + (size_t)y * W + x;
    row.c = *reinterpret_cast<const float4*>(p);
    row.l = (x > 0)     ? p[-1] : 0.f;
    row.r = (x + 4 < W) ? p[4]  : 0.f;
    return row;
}

__device__ __forceinline__ float4 hconv(const Row& row, float wl, float wc, float wr) {
    float4 o;
    o.x = fmaf(wl, row.l,   fmaf(wc, row.c.x, wr * row.c.y));
    o.y = fmaf(wl, row.c.x, fmaf(wc, row.c.y, wr * row.c.z));
    o.z = fmaf(wl, row.c.y, fmaf(wc, row.c.z, wr * row.c.w));
    o.w = fmaf(wl, row.c.z, fmaf(wc, row.c.w, wr * row.r));
    return o;
}

__device__ __forceinline__ float4 conv3(const Row& ra, const Row& rb, const Row& rc,
                                        const float* __restrict__ w) {
    float4 top = hconv(ra, w[0], w[1], w[2]);
    float4 mid = hconv(rb, w[3], w[4], w[5]);
    float4 bot = hconv(rc, w[6], w[7], w[8]);
    float4 o;
    o.x = top.x + mid.x + bot.x;
    o.y = top.y + mid.y + bot.y;
    o.z = top.z + mid.z + bot.z;
    o.w = top.w + mid.w + bot.w;
    return o;
}

// One 4-row strip. GT guards the top halo row (y0-1), GB guards the bottom
// halo row (y0+4). Loads are issued one full row-compute ahead of use.
template <bool GT, bool GB>
__device__ __forceinline__ void run_strip(const float* __restrict__ img,
                                          float* __restrict__ out,
                                          const float* __restrict__ w,
                                          int y0, int x) {
    float4* o0 = reinterpret_cast<float4*>(out + (size_t)y0 * W + x);

    // Front-batch: 3 rows (9 independent LDGs) before any compute.
    Row r0 = load_row<GT>(img, y0 - 1, x);
    Row r1 = load_row<false>(img, y0,     x);
    Row r2 = load_row<false>(img, y0 + 1, x);

    Row r3 = load_row<false>(img, y0 + 2, x);          // prefetch
    __stcs(o0, conv3(r0, r1, r2, w));                  // out y0

    Row r4 = load_row<false>(img, y0 + 3, x);          // prefetch
    __stcs(o0 + (W / 4), conv3(r1, r2, r3, w));        // out y0+1

    Row r5 = load_row<GB>(img, y0 + 4, x);             // prefetch (may be row H)
    __stcs(o0 + 2 * (W / 4), conv3(r2, r3, r4, w));    // out y0+2

    __stcs(o0 + 3 * (W / 4), conv3(r3, r4, r5, w));    // out y0+3
}

__global__ __launch_bounds__(TPB, 12) void gauss3x3_kernel(
    const float* __restrict__ input,
    const float* __restrict__ weight,
    const float* __restrict__ weight_factor,
    float* __restrict__ output,
    int n_mult)
{
    int z = blockIdx.z;
    int b = z % B;
    int m = z / B;

    // Build the 9-tap kernel (matches reference clamp/round semantics).
    float wf = weight_factor[m];
    wf = clampf(wf, 1.001f, 254.999f);
    wf = clampf(wf, 1.0f, 255.0f);
    float w[9];
#pragma unroll
    for (int k = 0; k < 9; k++) {
        float wc = weight[m * 9 + k];
        wc = clampf(wc, 0.001f, 0.999f);
        wc = clampf(wc, 0.0f, 1.0f);
        float q = rintf(wc * wf);          // RNE, same as jnp.round
        w[k] = fmaxf(q, 0.001f);
    }

    const float* img = input + (size_t)b * H * W;
    float* out = output + ((size_t)m * B + b) * H * W;

    int x  = threadIdx.x * 4;
    int y0 = blockIdx.y * ROWS;

    if (blockIdx.y == 0 || blockIdx.y == gridDim.y - 1) {
        run_strip<true, true>(img, out, w, y0, x);   // edge strips: guard both
    } else {
        run_strip<false, false>(img, out, w, y0, x); // interior: no predication
    }
}

extern "C" void kernel_launch(void* const* d_in, const int* in_sizes, int n_in,
                              void* d_out, int out_size) {
    const float* input  = (const float*)d_in[0];
    const float* weight = (const float*)d_in[1];
    const float* wfac   = (const float*)d_in[2];
    float* output       = (float*)d_out;

    int n_mult = in_sizes[1] / 9;   // = 1 for this shape

    dim3 block(TPB, 1, 1);
    dim3 grid(1, H / ROWS, B * n_mult);
    gauss3x3_kernel<<<grid, block>>>(input, weight, wfac, output, n_mult);
}

// round 11
// speedup vs baseline: 1.1839x; 1.1839x over previous
#include <cuda_runtime.h>

// Gaussian_Forward_Model: 3x3 conv, padding=1 (zeros), kernel built from
// weight (clamped) * weight_factor (clamped), rounded (RNE), min-clamped.
// input: [B=64, C=1, H=512, W=512] fp32
// output: [N_MULT, B, 1, H, W] fp32
//
// R6: R1's winning shape (ROWS=8, scalar halo, plain stores, 4096 blocks)
// plus a one-row-deeper full-Row software prefetch (2 rows of loads in
// flight per thread instead of 1) and interior-strip template
// specialization (62/64 strips fully unpredicated).

#define B 64
#define H 512
#define W 512
#define ROWS 8              // output rows per thread
#define TPB 128             // 128 threads * 4 floats = 512 = W

__device__ __forceinline__ float clampf(float v, float lo, float hi) {
    return fminf(fmaxf(v, lo), hi);
}

struct Row {
    float l;    // x-1
    float4 c;   // x..x+3
    float r;    // x+4
};

template <bool GUARD>
__device__ __forceinline__ Row load_row(const float* __restrict__ img, int y, int x) {
    Row row;
    if (GUARD) {
        if (y < 0 || y >= H) {
            row.l = 0.f; row.r = 0.f;
            row.c = make_float4(0.f, 0.f, 0.f, 0.f);
            return row;
        }
    }
    const float* p = img + (size_t)y * W + x;
    row.c = *reinterpret_cast<const float4*>(p);
    row.l = (x > 0)     ? p[-1] : 0.f;
    row.r = (x + 4 < W) ? p[4]  : 0.f;
    return row;
}

__device__ __forceinline__ float4 hconv(const Row& row, float wl, float wc, float wr) {
    float4 o;
    o.x = fmaf(wl, row.l,   fmaf(wc, row.c.x, wr * row.c.y));
    o.y = fmaf(wl, row.c.x, fmaf(wc, row.c.y, wr * row.c.z));
    o.z = fmaf(wl, row.c.y, fmaf(wc, row.c.z, wr * row.c.w));
    o.w = fmaf(wl, row.c.z, fmaf(wc, row.c.w, wr * row.r));
    return o;
}

__device__ __forceinline__ float4 conv3(const Row& ra, const Row& rb, const Row& rc,
                                        const float* __restrict__ w) {
    float4 top = hconv(ra, w[0], w[1], w[2]);
    float4 mid = hconv(rb, w[3], w[4], w[5]);
    float4 bot = hconv(rc, w[6], w[7], w[8]);
    float4 o;
    o.x = top.x + mid.x + bot.x;
    o.y = top.y + mid.y + bot.y;
    o.z = top.z + mid.z + bot.z;
    o.w = top.w + mid.w + bot.w;
    return o;
}

// GUARD covers the out-of-range halo rows (top strip: y0-1; bottom strip:
// y0+ROWS and the over-prefetch y0+ROWS+? — all y-loads are guarded when set).
template <bool GUARD>
__device__ __forceinline__ void run_strip(const float* __restrict__ img,
                                          float* __restrict__ out,
                                          const float* __restrict__ w,
                                          int y0, int x) {
    float4* op = reinterpret_cast<float4*>(out + (size_t)y0 * W + x);

    // Pipeline fill: rows y0-1, y0 complete, plus prefetched row y0+1.
    Row ra = load_row<GUARD>(img, y0 - 1, x);
    Row rb = load_row<false>(img, y0,     x);
    Row rn = load_row<false>(img, y0 + 1, x);   // "next" row, 1 iter ahead

#pragma unroll
    for (int i = 0; i < ROWS; i++) {
        // Issue the Row needed by iteration i+1 before computing iteration i.
        // For interior strips y0+i+2 <= y0+9 <= 505 < H, so unguarded.
        Row rn2;
        if (i < ROWS - 1) {
            rn2 = load_row<GUARD>(img, y0 + i + 2, x);
        } else {
            rn2.l = 0.f; rn2.r = 0.f;
            rn2.c = make_float4(0.f, 0.f, 0.f, 0.f);
        }

        Row rc = rn;
        op[(size_t)i * (W / 4)] = conv3(ra, rb, rc, w);

        ra = rb;
        rb = rc;
        rn = rn2;
    }
}

__global__ __launch_bounds__(TPB) void gauss3x3_kernel(
    const float* __restrict__ input,
    const float* __restrict__ weight,
    const float* __restrict__ weight_factor,
    float* __restrict__ output,
    int n_mult)
{
    int z = blockIdx.z;
    int b = z % B;
    int m = z / B;

    // Build the 9-tap kernel (matches reference clamp/round semantics).
    float wf = weight_factor[m];
    wf = clampf(wf, 1.001f, 254.999f);
    wf = clampf(wf, 1.0f, 255.0f);
    float w[9];
#pragma unroll
    for (int k = 0; k < 9; k++) {
        float wc = weight[m * 9 + k];
        wc = clampf(wc, 0.001f, 0.999f);
        wc = clampf(wc, 0.0f, 1.0f);
        float q = rintf(wc * wf);          // RNE, same as jnp.round
        w[k] = fmaxf(q, 0.001f);
    }

    const float* img = input + (size_t)b * H * W;
    float* out = output + ((size_t)m * B + b) * H * W;

    int x  = threadIdx.x * 4;
    int y0 = blockIdx.y * ROWS;

    if (blockIdx.y == 0 || blockIdx.y == gridDim.y - 1) {
        run_strip<true>(img, out, w, y0, x);
    } else {
        run_strip<false>(img, out, w, y0, x);
    }
}

extern "C" void kernel_launch(void* const* d_in, const int* in_sizes, int n_in,
                              void* d_out, int out_size) {
    const float* input  = (const float*)d_in[0];
    const float* weight = (const float*)d_in[1];
    const float* wfac   = (const float*)d_in[2];
    float* output       = (float*)d_out;

    int n_mult = in_sizes[1] / 9;   // = 1 for this shape

    dim3 block(TPB, 1, 1);
    dim3 grid(1, H / ROWS, B * n_mult);
    gauss3x3_kernel<<<grid, block>>>(input, weight, wfac, output, n_mult);
}